// round 1
// baseline (speedup 1.0000x reference)
#include <cuda_runtime.h>
#include <float.h>

// Problem constants
#define Bn    8
#define Nn    256
#define Dd    128
#define MIDn  128
#define FEATn 256   // 2*D

// Scratch (device globals: no runtime allocation allowed)
__device__ float g_msg1[Bn * Nn * MIDn];   // (B,N,MID)
__device__ float g_msg2[Bn * Nn * MIDn];   // (B,N,MID)
__device__ float g_msgg[Bn * MIDn];        // (B,MID)
__device__ float g_base[Bn * Nn * MIDn];   // features@Wo1 + bo1 + bo2

// ---- packed f32x2 helpers (sm_103a) ------------------------------------
__device__ __forceinline__ unsigned long long pack2(float lo, float hi) {
    unsigned long long u;
    asm("mov.b64 %0, {%1, %2};" : "=l"(u) : "f"(lo), "f"(hi));
    return u;
}
__device__ __forceinline__ void unpack2(unsigned long long u, float& lo, float& hi) {
    asm("mov.b64 {%0, %1}, %2;" : "=f"(lo), "=f"(hi) : "l"(u));
}
__device__ __forceinline__ void ffma2(unsigned long long& d,
                                      unsigned long long a,
                                      unsigned long long b) {
    asm("fma.rn.f32x2 %0, %1, %2, %0;" : "+l"(d) : "l"(a), "l"(b));
}

// ========================================================================
// Kernel 1: msg_1, msg_2, base  (features = concat(n_features, hidden))
// 8 rows per block, 128 threads (thread = output channel m).
// ========================================================================
__global__ __launch_bounds__(128) void prep_kernel(
    const float* __restrict__ hidden, const float* __restrict__ nfeat,
    const float* __restrict__ W1, const float* __restrict__ b1,
    const float* __restrict__ W2, const float* __restrict__ b2,
    const float* __restrict__ Wo1, const float* __restrict__ bo1,
    const float* __restrict__ bo2)
{
    const int R = 8;
    __shared__ float fs[R * FEATn];
    const int m = threadIdx.x;
    const int row0 = blockIdx.x * R;   // flattened (b,n) row

    #pragma unroll
    for (int r = 0; r < R; r++) {
        const int row = row0 + r;
        fs[r * FEATn + m]      = nfeat[row * Dd + m];    // features[:,0:128]
        fs[r * FEATn + Dd + m] = hidden[row * Dd + m];   // features[:,128:256]
    }
    __syncthreads();

    float a1[R], a2[R], ao[R];
    const float bb1 = b1[m];
    const float bb2 = b2[m];
    const float bbo = bo1[m] + bo2[m];
    #pragma unroll
    for (int r = 0; r < R; r++) { a1[r] = bb1; a2[r] = bb2; ao[r] = bbo; }

    for (int f = 0; f < FEATn; f++) {
        const float w1 = __ldg(&W1[f * MIDn + m]);
        const float w2 = __ldg(&W2[f * MIDn + m]);
        const float wo = __ldg(&Wo1[f * MIDn + m]);
        #pragma unroll
        for (int r = 0; r < R; r++) {
            const float s = fs[r * FEATn + f];
            a1[r] = fmaf(s, w1, a1[r]);
            a2[r] = fmaf(s, w2, a2[r]);
            ao[r] = fmaf(s, wo, ao[r]);
        }
    }
    #pragma unroll
    for (int r = 0; r < R; r++) {
        g_msg1[(row0 + r) * MIDn + m] = a1[r];
        g_msg2[(row0 + r) * MIDn + m] = a2[r];
        g_base[(row0 + r) * MIDn + m] = ao[r];
    }
}

// ========================================================================
// Kernel 2: msg_g = g_features @ Wg + bg   (tiny)
// ========================================================================
__global__ __launch_bounds__(128) void msgg_kernel(
    const float* __restrict__ gfeat, const float* __restrict__ Wg,
    const float* __restrict__ bg)
{
    const int m = threadIdx.x;
    const int b = blockIdx.x;
    float acc = bg[m];
    for (int k = 0; k < Dd; k++)
        acc = fmaf(gfeat[b * Dd + k], __ldg(&Wg[k * MIDn + m]), acc);
    g_msgg[b * MIDn + m] = acc;
}

// ========================================================================
// Kernel 3 (fused main pass): one CTA per (b, j).
//   out[b,j,m] = base[b,j,m]
//              + sum_k Wo2[k,m] * max_i adj[b,i,j] *
//                    ( e[b,i,j,:]@We[:,m] + be[m]
//                      + msg1[b,j,m] + msg2[b,i,m] + msgg[b,m] )
// We column held in 64 packed f32x2 registers; e rows staged via smem in
// 8-row chunks; dot via two fma.rn.f32x2 chains.
// ========================================================================
__global__ __launch_bounds__(128, 2) void main_kernel(
    const float* __restrict__ efeat, const float* __restrict__ adj,
    const float* __restrict__ We,    const float* __restrict__ be,
    const float* __restrict__ Wo2,   float* __restrict__ out)
{
    __shared__ __align__(16) float esm[8 * Dd];     // 8 e-rows
    __shared__ float m2sm[8 * MIDn];                // matching msg2 rows
    __shared__ float adjsm[8];
    __shared__ float msgsm[MIDn];

    const int m  = threadIdx.x;
    const int bj = blockIdx.x;       // b*256 + j
    const int b  = bj >> 8;
    const int j  = bj & 255;

    // We[:,m] packed into 64 f32x2 registers (k-pairs)
    unsigned long long w2[64];
    #pragma unroll
    for (int kk = 0; kk < 64; kk++)
        w2[kk] = pack2(__ldg(&We[(2 * kk) * MIDn + m]),
                       __ldg(&We[(2 * kk + 1) * MIDn + m]));

    const float cst = g_msg1[bj * MIDn + m] + g_msgg[b * MIDn + m] + be[m];
    float best = -FLT_MAX;

    const float* ebase  = efeat + ((long)b * Nn * Nn + j) * Dd;  // + i*Nn*Dd
    const float* m2base = g_msg2 + b * Nn * MIDn;
    const float* adjbase = adj + (long)(b * Nn) * Nn + j;        // + i*Nn

    for (int c = 0; c < Nn / 8; c++) {
        // stage 8 rows of e and msg2 (coalesced), 8 adj scalars
        #pragma unroll
        for (int r = 0; r < 8; r++) {
            const int i = c * 8 + r;
            esm[r * Dd + m]    = ebase[(long)i * Nn * Dd + m];
            m2sm[r * MIDn + m] = m2base[i * MIDn + m];
        }
        if (m < 8) adjsm[m] = adjbase[(long)(c * 8 + m) * Nn];
        __syncthreads();

        #pragma unroll 1
        for (int r = 0; r < 8; r++) {
            const ulonglong2* er = (const ulonglong2*)(esm + r * Dd);
            unsigned long long acc0 = 0ull, acc1 = 0ull;   // {0.f,0.f}
            #pragma unroll
            for (int q = 0; q < 32; q++) {
                const ulonglong2 ev = er[q];               // e[4q..4q+3]
                ffma2(acc0, ev.x, w2[2 * q]);
                ffma2(acc1, ev.y, w2[2 * q + 1]);
            }
            float x0, x1, y0, y1;
            unpack2(acc0, x0, x1);
            unpack2(acc1, y0, y1);
            const float dot = (x0 + y0) + (x1 + y1);
            const float msg = dot + cst + m2sm[r * MIDn + m];
            best = fmaxf(best, adjsm[r] * msg);
        }
        __syncthreads();
    }

    // epilogue: out = base + msgs @ Wo2
    msgsm[m] = best;
    __syncthreads();
    float o = g_base[bj * MIDn + m];
    for (int k = 0; k < MIDn; k++)
        o = fmaf(msgsm[k], __ldg(&Wo2[k * MIDn + m]), o);
    out[bj * MIDn + m] = o;
}

// ========================================================================
extern "C" void kernel_launch(void* const* d_in, const int* in_sizes, int n_in,
                              void* d_out, int out_size)
{
    const float* hidden = (const float*)d_in[0];
    const float* nfeat  = (const float*)d_in[1];
    const float* efeat  = (const float*)d_in[2];
    const float* gfeat  = (const float*)d_in[3];
    const float* adj    = (const float*)d_in[4];
    const float* W1  = (const float*)d_in[5];
    const float* b1  = (const float*)d_in[6];
    const float* W2  = (const float*)d_in[7];
    const float* b2  = (const float*)d_in[8];
    const float* We  = (const float*)d_in[9];
    const float* be  = (const float*)d_in[10];
    const float* Wg  = (const float*)d_in[11];
    const float* bg  = (const float*)d_in[12];
    const float* Wo1 = (const float*)d_in[13];
    const float* bo1 = (const float*)d_in[14];
    const float* Wo2 = (const float*)d_in[15];
    const float* bo2 = (const float*)d_in[16];
    float* out = (float*)d_out;

    prep_kernel<<<(Bn * Nn) / 8, 128>>>(hidden, nfeat, W1, b1, W2, b2,
                                        Wo1, bo1, bo2);
    msgg_kernel<<<Bn, 128>>>(gfeat, Wg, bg);
    main_kernel<<<Bn * Nn, 128>>>(efeat, adj, We, be, Wo2, out);
}